// round 10
// baseline (speedup 1.0000x reference)
#include <cuda_runtime.h>

#define Bq 8
#define Nq 512
#define Fq 128
#define Hq 4
#define Uq 32
#define HU (Hq*Uq)
#define LOG2E 1.4426950408889634f
#define NJC 8   /* j-chunks of 64 */

typedef unsigned long long u64;

// ---- packed f32x2 helpers (sm_103a; PTX-only) -----------------------------
__device__ __forceinline__ u64 pk2(float lo, float hi) {
    u64 r; asm("mov.b64 %0,{%1,%2};" : "=l"(r) : "f"(lo), "f"(hi)); return r;
}
__device__ __forceinline__ void upk2(u64 v, float& lo, float& hi) {
    asm("mov.b64 {%0,%1},%2;" : "=f"(lo), "=f"(hi) : "l"(v));
}
__device__ __forceinline__ u64 add2(u64 a, u64 b) {
    u64 r; asm("add.rn.f32x2 %0,%1,%2;" : "=l"(r) : "l"(a), "l"(b)); return r;
}
__device__ __forceinline__ u64 fma2(u64 a, u64 b, u64 c) {
    u64 r; asm("fma.rn.f32x2 %0,%1,%2,%3;" : "=l"(r) : "l"(a), "l"(b), "l"(c)); return r;
}
__device__ __forceinline__ u64 relu2(u64 v) {
    float lo, hi; upk2(v, lo, hi);
    return pk2(fmaxf(lo, 0.f), fmaxf(hi, 0.f));   // 2x FMNMX, alu pipe
}
__device__ __forceinline__ float ex2f(float x) {
    float r; asm("ex2.approx.f32 %0,%1;" : "=f"(r) : "f"(x)); return r;
}

// Scratch (device globals: allocation-free)
__device__ float g_Hsrc[Bq*Hq*Nq*Uq];                 // 2 MB
__device__ float g_Hdst[Bq*Hq*Nq*Uq];                 // 2 MB
__device__ float g_Pl  [Bq*Hq*NJC*Nq];                // [bh][jc][i]
__device__ float g_Pacc[Bq*Hq*NJC*Nq*2*16];           // [bh][jc][i][uh][16]

// ---------------------------------------------------------------------------
// Kernel 1: projections — measured-best config (14.8us). UNCHANGED.
// ---------------------------------------------------------------------------
__global__ void __launch_bounds__(512)
proj_kernel(const float* __restrict__ inp,
            const float* __restrict__ Wsrc,
            const float* __restrict__ Wdst)
{
    extern __shared__ float sm[];
    float* sIn = sm;             // [128][132]
    float* sW  = sm + 128*132;   // [128][64]

    const int tid  = threadIdx.x;
    const int h    = blockIdx.y;
    const int row0 = blockIdx.x * 128;

    for (int t = tid; t < 128*32; t += 512) {
        int r = t >> 5, c = t & 31;
        reinterpret_cast<float4*>(sIn + r*132)[c] =
            reinterpret_cast<const float4*>(inp + (row0 + r)*Fq)[c];
    }
    for (int t = tid; t < 128*8; t += 512) {
        int k = t >> 3, c = t & 7;
        reinterpret_cast<float4*>(sW + k*64)[c] =
            reinterpret_cast<const float4*>(Wsrc + (h*Fq + k)*Uq)[c];
        reinterpret_cast<float4*>(sW + k*64 + 32)[c] =
            reinterpret_cast<const float4*>(Wdst + (h*Fq + k)*Uq)[c];
    }
    __syncthreads();

    const int tx = tid & 15;
    const int ty = tid >> 4;

    u64 acc[4][2];
    #pragma unroll
    for (int r = 0; r < 4; r++) { acc[r][0] = 0ull; acc[r][1] = 0ull; }

    for (int k0 = 0; k0 < 128; k0 += 4) {
        float rvr[4][4];
        #pragma unroll
        for (int r = 0; r < 4; r++) {
            float4 v = *reinterpret_cast<const float4*>(sIn + (ty*4 + r)*132 + k0);
            rvr[r][0] = v.x; rvr[r][1] = v.y; rvr[r][2] = v.z; rvr[r][3] = v.w;
        }
        #pragma unroll
        for (int kk = 0; kk < 4; kk++) {
            float4 cv = reinterpret_cast<const float4*>(sW + (k0 + kk)*64)[tx];
            u64 c01 = pk2(cv.x, cv.y), c23 = pk2(cv.z, cv.w);
            #pragma unroll
            for (int r = 0; r < 4; r++) {
                u64 rp = pk2(rvr[r][kk], rvr[r][kk]);
                acc[r][0] = fma2(rp, c01, acc[r][0]);
                acc[r][1] = fma2(rp, c23, acc[r][1]);
            }
        }
    }

    const int b = row0 >> 9;
    float* dstp = (tx < 8) ? g_Hsrc : g_Hdst;
    const int c4 = tx & 7;
    #pragma unroll
    for (int r = 0; r < 4; r++) {
        int n = (row0 + ty*4 + r) & (Nq - 1);
        float o0, o1, o2v, o3; upk2(acc[r][0], o0, o1); upk2(acc[r][1], o2v, o3);
        reinterpret_cast<float4*>(dstp + ((b*Hq + h)*Nq + n)*Uq)[c4] =
            make_float4(o0, o1, o2v, o3);
    }
}

// ---------------------------------------------------------------------------
// Kernel 2: attention. R8 structure (FMNMX relu), (128,7) = 7 warps/SMSP.
// 64i x 64j, 128 thr = 64 rows x 2 uh. Query row read from L2 (no sh_q).
// ---------------------------------------------------------------------------
__global__ void __launch_bounds__(128, 7)
attn_kernel(const float* __restrict__ Av)
{
    extern __shared__ float sm[];
    float* sh_v = sm;                 // [64][32]
    float* sh_d = sm + 64*Uq;         // [64][32]
    float* sh_c = sh_d + 64*Uq;       // [64]

    const int tid = threadIdx.x;
    const int ib  = blockIdx.x;
    const int jc  = blockIdx.y;
    const int bh  = blockIdx.z;
    const int h   = bh & 3;

    const float* Hs = g_Hsrc + bh*Nq*Uq;
    const float* Hd = g_Hdst + bh*Nq*Uq;

    for (int t = tid; t < 64*Uq/4; t += 128) {
        reinterpret_cast<float4*>(sh_v)[t] =
            reinterpret_cast<const float4*>(Hs + jc*64*Uq)[t];
        reinterpret_cast<float4*>(sh_d)[t] =
            reinterpret_cast<const float4*>(Hd + jc*64*Uq)[t];
    }
    __syncthreads();

    if (tid < 64) {
        const float4* dr = reinterpret_cast<const float4*>(sh_d + tid*Uq);
        const float4* ar = reinterpret_cast<const float4*>(Av + h*Uq);
        float s = 0.f;
        #pragma unroll
        for (int q = 0; q < 8; q++) {
            float4 d = dr[q], a = ar[q];
            s += d.x*a.x + d.y*a.y + d.z*a.z + d.w*a.w;
        }
        sh_c[tid] = (0.2f*LOG2E) * s;
    }
    __syncthreads();

    const int row = tid >> 1;          // 0..63
    const int uh  = tid & 1;           // shfl partner = lane^1
    const int ub  = uh*16;

    u64 s2[8], a2p[8], acc[8];
    {
        const ulonglong2* sp = reinterpret_cast<const ulonglong2*>(
            Hs + (ib*64 + row)*Uq + ub);
        #pragma unroll
        for (int q = 0; q < 4; q++) {
            ulonglong2 t2 = sp[q];
            s2[2*q] = t2.x; s2[2*q+1] = t2.y;
        }
        const float4* ap = reinterpret_cast<const float4*>(Av + h*Uq + ub);
        #pragma unroll
        for (int q = 0; q < 4; q++) {
            float4 a = ap[q];
            const float sA = 0.8f*LOG2E;
            a2p[2*q]   = pk2(sA*a.x, sA*a.y);
            a2p[2*q+1] = pk2(sA*a.z, sA*a.w);
        }
    }
    #pragma unroll
    for (int q = 0; q < 8; q++) acc[q] = 0ull;
    float l = 0.f;

    #pragma unroll 4
    for (int j = 0; j < 64; j++) {
        const ulonglong2* dp = reinterpret_cast<const ulonglong2*>(sh_d + j*Uq + ub);
        ulonglong2 d0 = dp[0], d1 = dp[1];
        u64 pa = fma2(a2p[0], relu2(add2(s2[0], d0.x)), 0ull);
        u64 pb = fma2(a2p[1], relu2(add2(s2[1], d0.y)), 0ull);
        pa = fma2(a2p[2], relu2(add2(s2[2], d1.x)), pa);
        pb = fma2(a2p[3], relu2(add2(s2[3], d1.y)), pb);
        ulonglong2 d2 = dp[2], d3 = dp[3];
        pa = fma2(a2p[4], relu2(add2(s2[4], d2.x)), pa);
        pb = fma2(a2p[5], relu2(add2(s2[5], d2.y)), pb);
        pa = fma2(a2p[6], relu2(add2(s2[6], d3.x)), pa);
        pb = fma2(a2p[7], relu2(add2(s2[7], d3.y)), pb);
        u64 p2 = add2(pa, pb);
        float plo, phi; upk2(p2, plo, phi);
        float ps = plo + phi;
        ps += __shfl_xor_sync(0xffffffffu, ps, 1);
        float p = ex2f(ps + sh_c[j]);
        l += p;
        u64 pp = pk2(p, p);
        const ulonglong2* vp = reinterpret_cast<const ulonglong2*>(sh_v + j*Uq + ub);
        ulonglong2 v0 = vp[0], v1 = vp[1];
        acc[0] = fma2(pp, v0.x, acc[0]);
        acc[1] = fma2(pp, v0.y, acc[1]);
        acc[2] = fma2(pp, v1.x, acc[2]);
        acc[3] = fma2(pp, v1.y, acc[3]);
        ulonglong2 v2 = vp[2], v3 = vp[3];
        acc[4] = fma2(pp, v2.x, acc[4]);
        acc[5] = fma2(pp, v2.y, acc[5]);
        acc[6] = fma2(pp, v3.x, acc[6]);
        acc[7] = fma2(pp, v3.y, acc[7]);
    }

    const int i   = ib*64 + row;
    const int rec = (bh*NJC + jc)*Nq + i;
    if (uh == 0) g_Pl[rec] = l;
    float* pa_ = g_Pacc + (rec*2 + uh)*16;
    #pragma unroll
    for (int q = 0; q < 4; q++) {
        float x0, x1, x2, x3;
        upk2(acc[2*q], x0, x1); upk2(acc[2*q+1], x2, x3);
        reinterpret_cast<float4*>(pa_)[q] = make_float4(x0, x1, x2, x3);
    }
}

// ---------------------------------------------------------------------------
// Kernel 3: combine NJC partials + normalize. 32768 threads.
// ---------------------------------------------------------------------------
__global__ void __launch_bounds__(256)
combine_kernel(float* __restrict__ out)
{
    const int idx = blockIdx.x*256 + threadIdx.x;   // (bh, i, uh)
    const int uh = idx & 1;
    const int i  = (idx >> 1) & (Nq - 1);
    const int bh = idx >> 10;
    const int b = bh >> 2, h = bh & 3;

    float l = 0.f;
    float4 s0 = make_float4(0.f,0.f,0.f,0.f), s1 = s0, s2v = s0, s3 = s0;
    #pragma unroll
    for (int jc = 0; jc < NJC; jc++) {
        const int rec = (bh*NJC + jc)*Nq + i;
        l += g_Pl[rec];
        const float4* A = reinterpret_cast<const float4*>(g_Pacc + (rec*2 + uh)*16);
        float4 a0 = A[0], a1 = A[1], a2 = A[2], a3 = A[3];
        s0.x+=a0.x; s0.y+=a0.y; s0.z+=a0.z; s0.w+=a0.w;
        s1.x+=a1.x; s1.y+=a1.y; s1.z+=a1.z; s1.w+=a1.w;
        s2v.x+=a2.x; s2v.y+=a2.y; s2v.z+=a2.z; s2v.w+=a2.w;
        s3.x+=a3.x; s3.y+=a3.y; s3.z+=a3.z; s3.w+=a3.w;
    }
    const float inv = __frcp_rn(l);
    float* op = out + (b*Nq + i)*HU + h*Uq + uh*16;
    reinterpret_cast<float4*>(op)[0] = make_float4(s0.x*inv, s0.y*inv, s0.z*inv, s0.w*inv);
    reinterpret_cast<float4*>(op)[1] = make_float4(s1.x*inv, s1.y*inv, s1.z*inv, s1.w*inv);
    reinterpret_cast<float4*>(op)[2] = make_float4(s2v.x*inv, s2v.y*inv, s2v.z*inv, s2v.w*inv);
    reinterpret_cast<float4*>(op)[3] = make_float4(s3.x*inv, s3.y*inv, s3.z*inv, s3.w*inv);
}

// ---------------------------------------------------------------------------
extern "C" void kernel_launch(void* const* d_in, const int* in_sizes, int n_in,
                              void* d_out, int out_size)
{
    const float* inp  = (const float*)d_in[0];
    const float* Wsrc = (const float*)d_in[1];
    const float* Wdst = (const float*)d_in[2];
    const float* Av   = (const float*)d_in[3];
    float* out = (float*)d_out;

    const int PROJ_SMEM = (128*132 + 128*64) * 4;          // 100,352 B
    const int ATTN_SMEM = (2*64*Uq + 64) * 4;              //  16,640 B
    cudaFuncSetAttribute(proj_kernel,
        cudaFuncAttributeMaxDynamicSharedMemorySize, PROJ_SMEM);
    cudaFuncSetAttribute(attn_kernel,
        cudaFuncAttributeMaxDynamicSharedMemorySize, ATTN_SMEM);

    proj_kernel<<<dim3(Bq*Nq/128, Hq), 512, PROJ_SMEM>>>(inp, Wsrc, Wdst);
    attn_kernel<<<dim3(Nq/64, NJC, Bq*Hq), 128, ATTN_SMEM>>>(Av);
    combine_kernel<<<Bq*Hq*Nq*2/256, 256>>>(out);
}

// round 11
// speedup vs baseline: 1.0606x; 1.0606x over previous
#include <cuda_runtime.h>

#define Bq 8
#define Nq 512
#define Fq 128
#define Hq 4
#define Uq 32
#define HU (Hq*Uq)
#define LOG2E 1.4426950408889634f
#define NJC 8   /* j-chunks of 64 */

typedef unsigned long long u64;

// ---- packed f32x2 helpers (sm_103a; PTX-only) -----------------------------
__device__ __forceinline__ u64 pk2(float lo, float hi) {
    u64 r; asm("mov.b64 %0,{%1,%2};" : "=l"(r) : "f"(lo), "f"(hi)); return r;
}
__device__ __forceinline__ void upk2(u64 v, float& lo, float& hi) {
    asm("mov.b64 {%0,%1},%2;" : "=f"(lo), "=f"(hi) : "l"(v));
}
__device__ __forceinline__ u64 add2(u64 a, u64 b) {
    u64 r; asm("add.rn.f32x2 %0,%1,%2;" : "=l"(r) : "l"(a), "l"(b)); return r;
}
__device__ __forceinline__ u64 fma2(u64 a, u64 b, u64 c) {
    u64 r; asm("fma.rn.f32x2 %0,%1,%2,%3;" : "=l"(r) : "l"(a), "l"(b), "l"(c)); return r;
}
__device__ __forceinline__ u64 relu2(u64 v) {
    float lo, hi; upk2(v, lo, hi);
    return pk2(fmaxf(lo, 0.f), fmaxf(hi, 0.f));   // 2x FMNMX, alu pipe
}
__device__ __forceinline__ float ex2f(float x) {
    float r; asm("ex2.approx.f32 %0,%1;" : "=f"(r) : "f"(x)); return r;
}

// Scratch (device globals: allocation-free)
__device__ float g_Hsrc[Bq*Hq*Nq*Uq];                 // 2 MB
__device__ float g_Hdst[Bq*Hq*Nq*Uq];                 // 2 MB
__device__ float g_Pl  [Bq*Hq*NJC*Nq];                // [bh][jc][i]
__device__ float g_Pacc[Bq*Hq*NJC*Nq*2*16];           // [bh][jc][i][uh][16]

// ---------------------------------------------------------------------------
// Kernel 1: projections — measured-best config (14.8us). UNCHANGED.
// ---------------------------------------------------------------------------
__global__ void __launch_bounds__(512)
proj_kernel(const float* __restrict__ inp,
            const float* __restrict__ Wsrc,
            const float* __restrict__ Wdst)
{
    extern __shared__ float sm[];
    float* sIn = sm;             // [128][132]
    float* sW  = sm + 128*132;   // [128][64]

    const int tid  = threadIdx.x;
    const int h    = blockIdx.y;
    const int row0 = blockIdx.x * 128;

    for (int t = tid; t < 128*32; t += 512) {
        int r = t >> 5, c = t & 31;
        reinterpret_cast<float4*>(sIn + r*132)[c] =
            reinterpret_cast<const float4*>(inp + (row0 + r)*Fq)[c];
    }
    for (int t = tid; t < 128*8; t += 512) {
        int k = t >> 3, c = t & 7;
        reinterpret_cast<float4*>(sW + k*64)[c] =
            reinterpret_cast<const float4*>(Wsrc + (h*Fq + k)*Uq)[c];
        reinterpret_cast<float4*>(sW + k*64 + 32)[c] =
            reinterpret_cast<const float4*>(Wdst + (h*Fq + k)*Uq)[c];
    }
    __syncthreads();

    const int tx = tid & 15;
    const int ty = tid >> 4;

    u64 acc[4][2];
    #pragma unroll
    for (int r = 0; r < 4; r++) { acc[r][0] = 0ull; acc[r][1] = 0ull; }

    for (int k0 = 0; k0 < 128; k0 += 4) {
        float rvr[4][4];
        #pragma unroll
        for (int r = 0; r < 4; r++) {
            float4 v = *reinterpret_cast<const float4*>(sIn + (ty*4 + r)*132 + k0);
            rvr[r][0] = v.x; rvr[r][1] = v.y; rvr[r][2] = v.z; rvr[r][3] = v.w;
        }
        #pragma unroll
        for (int kk = 0; kk < 4; kk++) {
            float4 cv = reinterpret_cast<const float4*>(sW + (k0 + kk)*64)[tx];
            u64 c01 = pk2(cv.x, cv.y), c23 = pk2(cv.z, cv.w);
            #pragma unroll
            for (int r = 0; r < 4; r++) {
                u64 rp = pk2(rvr[r][kk], rvr[r][kk]);
                acc[r][0] = fma2(rp, c01, acc[r][0]);
                acc[r][1] = fma2(rp, c23, acc[r][1]);
            }
        }
    }

    const int b = row0 >> 9;
    float* dstp = (tx < 8) ? g_Hsrc : g_Hdst;
    const int c4 = tx & 7;
    #pragma unroll
    for (int r = 0; r < 4; r++) {
        int n = (row0 + ty*4 + r) & (Nq - 1);
        float o0, o1, o2v, o3; upk2(acc[r][0], o0, o1); upk2(acc[r][1], o2v, o3);
        reinterpret_cast<float4*>(dstp + ((b*Hq + h)*Nq + n)*Uq)[c4] =
            make_float4(o0, o1, o2v, o3);
    }
}

// ---------------------------------------------------------------------------
// Kernel 2: attention, R8 structure + manual 2x-unrolled software pipeline
// with alternating d-register buffers (dA/dB) and prefetched c.
// 64i x 64j, 128 thr = 64 rows x 2 uh, (128,6).
// ---------------------------------------------------------------------------
__global__ void __launch_bounds__(128, 6)
attn_kernel(const float* __restrict__ Av)
{
    extern __shared__ float sm[];
    float* sh_v = sm;                 // [64][32]
    float* sh_d = sm + 64*Uq;         // [64][32]
    float* sh_c = sh_d + 64*Uq;       // [64] (+pad row after, see ATTN_SMEM)

    const int tid = threadIdx.x;
    const int ib  = blockIdx.x;
    const int jc  = blockIdx.y;
    const int bh  = blockIdx.z;
    const int h   = bh & 3;

    const float* Hs = g_Hsrc + bh*Nq*Uq;
    const float* Hd = g_Hdst + bh*Nq*Uq;

    for (int t = tid; t < 64*Uq/4; t += 128) {
        reinterpret_cast<float4*>(sh_v)[t] =
            reinterpret_cast<const float4*>(Hs + jc*64*Uq)[t];
        reinterpret_cast<float4*>(sh_d)[t] =
            reinterpret_cast<const float4*>(Hd + jc*64*Uq)[t];
    }
    __syncthreads();

    if (tid < 64) {
        const float4* dr = reinterpret_cast<const float4*>(sh_d + tid*Uq);
        const float4* ar = reinterpret_cast<const float4*>(Av + h*Uq);
        float s = 0.f;
        #pragma unroll
        for (int q = 0; q < 8; q++) {
            float4 d = dr[q], a = ar[q];
            s += d.x*a.x + d.y*a.y + d.z*a.z + d.w*a.w;
        }
        sh_c[tid] = (0.2f*LOG2E) * s;
    }
    __syncthreads();

    const int row = tid >> 1;          // 0..63
    const int uh  = tid & 1;           // shfl partner = lane^1
    // ulonglong2 layout: one row = 8 x 16B; this thread's half starts at uh*4
    const ulonglong2* dT = reinterpret_cast<const ulonglong2*>(sh_d) + uh*4;
    const ulonglong2* vT = reinterpret_cast<const ulonglong2*>(sh_v) + uh*4;

    u64 s2[8], a2p[8], acc[8];
    {
        const ulonglong2* sp = reinterpret_cast<const ulonglong2*>(
            Hs + (ib*64 + row)*Uq + uh*16);
        #pragma unroll
        for (int q = 0; q < 4; q++) {
            ulonglong2 t2 = sp[q];
            s2[2*q] = t2.x; s2[2*q+1] = t2.y;
        }
        const float4* ap = reinterpret_cast<const float4*>(Av + h*Uq + uh*16);
        #pragma unroll
        for (int q = 0; q < 4; q++) {
            float4 a = ap[q];
            const float sA = 0.8f*LOG2E;
            a2p[2*q]   = pk2(sA*a.x, sA*a.y);
            a2p[2*q+1] = pk2(sA*a.z, sA*a.w);
        }
    }
    #pragma unroll
    for (int q = 0; q < 8; q++) acc[q] = 0ull;
    float l = 0.f;

    // ---- software-pipelined j loop, manual 2x unroll, alternating buffers --
    ulonglong2 dA0, dA1, dA2, dA3, dB0, dB1, dB2, dB3;
    float cA, cB;
    dA0 = dT[0]; dA1 = dT[1]; dA2 = dT[2]; dA3 = dT[3];
    cA = sh_c[0];

    #pragma unroll 2
    for (int j = 0; j < 64; j += 2) {
        // ---- iter j (uses A, prefetches B = j+1) ----
        {
            const ulonglong2* dn = dT + (j+1)*8;
            dB0 = dn[0]; dB1 = dn[1]; dB2 = dn[2]; dB3 = dn[3];
            cB = sh_c[j+1];
            const ulonglong2* vp = vT + j*8;
            ulonglong2 v0 = vp[0], v1 = vp[1], v2 = vp[2], v3 = vp[3];

            u64 pa = fma2(a2p[0], relu2(add2(s2[0], dA0.x)), 0ull);
            u64 pb = fma2(a2p[1], relu2(add2(s2[1], dA0.y)), 0ull);
            pa = fma2(a2p[2], relu2(add2(s2[2], dA1.x)), pa);
            pb = fma2(a2p[3], relu2(add2(s2[3], dA1.y)), pb);
            pa = fma2(a2p[4], relu2(add2(s2[4], dA2.x)), pa);
            pb = fma2(a2p[5], relu2(add2(s2[5], dA2.y)), pb);
            pa = fma2(a2p[6], relu2(add2(s2[6], dA3.x)), pa);
            pb = fma2(a2p[7], relu2(add2(s2[7], dA3.y)), pb);
            u64 p2 = add2(pa, pb);
            float plo, phi; upk2(p2, plo, phi);
            float ps = plo + phi;
            ps += __shfl_xor_sync(0xffffffffu, ps, 1);
            float p = ex2f(ps + cA);
            l += p;
            u64 pp = pk2(p, p);
            acc[0] = fma2(pp, v0.x, acc[0]);
            acc[1] = fma2(pp, v0.y, acc[1]);
            acc[2] = fma2(pp, v1.x, acc[2]);
            acc[3] = fma2(pp, v1.y, acc[3]);
            acc[4] = fma2(pp, v2.x, acc[4]);
            acc[5] = fma2(pp, v2.y, acc[5]);
            acc[6] = fma2(pp, v3.x, acc[6]);
            acc[7] = fma2(pp, v3.y, acc[7]);
        }
        // ---- iter j+1 (uses B, prefetches A = j+2; padded row is harmless) --
        {
            const ulonglong2* dn = dT + (j+2)*8;
            dA0 = dn[0]; dA1 = dn[1]; dA2 = dn[2]; dA3 = dn[3];
            cA = sh_c[j+2];
            const ulonglong2* vp = vT + (j+1)*8;
            ulonglong2 v0 = vp[0], v1 = vp[1], v2 = vp[2], v3 = vp[3];

            u64 pa = fma2(a2p[0], relu2(add2(s2[0], dB0.x)), 0ull);
            u64 pb = fma2(a2p[1], relu2(add2(s2[1], dB0.y)), 0ull);
            pa = fma2(a2p[2], relu2(add2(s2[2], dB1.x)), pa);
            pb = fma2(a2p[3], relu2(add2(s2[3], dB1.y)), pb);
            pa = fma2(a2p[4], relu2(add2(s2[4], dB2.x)), pa);
            pb = fma2(a2p[5], relu2(add2(s2[5], dB2.y)), pb);
            pa = fma2(a2p[6], relu2(add2(s2[6], dB3.x)), pa);
            pb = fma2(a2p[7], relu2(add2(s2[7], dB3.y)), pb);
            u64 p2 = add2(pa, pb);
            float plo, phi; upk2(p2, plo, phi);
            float ps = plo + phi;
            ps += __shfl_xor_sync(0xffffffffu, ps, 1);
            float p = ex2f(ps + cB);
            l += p;
            u64 pp = pk2(p, p);
            acc[0] = fma2(pp, v0.x, acc[0]);
            acc[1] = fma2(pp, v0.y, acc[1]);
            acc[2] = fma2(pp, v1.x, acc[2]);
            acc[3] = fma2(pp, v1.y, acc[3]);
            acc[4] = fma2(pp, v2.x, acc[4]);
            acc[5] = fma2(pp, v2.y, acc[5]);
            acc[6] = fma2(pp, v3.x, acc[6]);
            acc[7] = fma2(pp, v3.y, acc[7]);
        }
    }

    const int i   = ib*64 + row;
    const int rec = (bh*NJC + jc)*Nq + i;
    if (uh == 0) g_Pl[rec] = l;
    float* pa_ = g_Pacc + (rec*2 + uh)*16;
    #pragma unroll
    for (int q = 0; q < 4; q++) {
        float x0, x1, x2, x3;
        upk2(acc[2*q], x0, x1); upk2(acc[2*q+1], x2, x3);
        reinterpret_cast<float4*>(pa_)[q] = make_float4(x0, x1, x2, x3);
    }
}

// ---------------------------------------------------------------------------
// Kernel 3: combine NJC partials + normalize. 32768 threads.
// ---------------------------------------------------------------------------
__global__ void __launch_bounds__(256)
combine_kernel(float* __restrict__ out)
{
    const int idx = blockIdx.x*256 + threadIdx.x;   // (bh, i, uh)
    const int uh = idx & 1;
    const int i  = (idx >> 1) & (Nq - 1);
    const int bh = idx >> 10;
    const int b = bh >> 2, h = bh & 3;

    float l = 0.f;
    float4 s0 = make_float4(0.f,0.f,0.f,0.f), s1 = s0, s2v = s0, s3 = s0;
    #pragma unroll
    for (int jc = 0; jc < NJC; jc++) {
        const int rec = (bh*NJC + jc)*Nq + i;
        l += g_Pl[rec];
        const float4* A = reinterpret_cast<const float4*>(g_Pacc + (rec*2 + uh)*16);
        float4 a0 = A[0], a1 = A[1], a2 = A[2], a3 = A[3];
        s0.x+=a0.x; s0.y+=a0.y; s0.z+=a0.z; s0.w+=a0.w;
        s1.x+=a1.x; s1.y+=a1.y; s1.z+=a1.z; s1.w+=a1.w;
        s2v.x+=a2.x; s2v.y+=a2.y; s2v.z+=a2.z; s2v.w+=a2.w;
        s3.x+=a3.x; s3.y+=a3.y; s3.z+=a3.z; s3.w+=a3.w;
    }
    const float inv = __frcp_rn(l);
    float* op = out + (b*Nq + i)*HU + h*Uq + uh*16;
    reinterpret_cast<float4*>(op)[0] = make_float4(s0.x*inv, s0.y*inv, s0.z*inv, s0.w*inv);
    reinterpret_cast<float4*>(op)[1] = make_float4(s1.x*inv, s1.y*inv, s1.z*inv, s1.w*inv);
    reinterpret_cast<float4*>(op)[2] = make_float4(s2v.x*inv, s2v.y*inv, s2v.z*inv, s2v.w*inv);
    reinterpret_cast<float4*>(op)[3] = make_float4(s3.x*inv, s3.y*inv, s3.z*inv, s3.w*inv);
}

// ---------------------------------------------------------------------------
extern "C" void kernel_launch(void* const* d_in, const int* in_sizes, int n_in,
                              void* d_out, int out_size)
{
    const float* inp  = (const float*)d_in[0];
    const float* Wsrc = (const float*)d_in[1];
    const float* Wdst = (const float*)d_in[2];
    const float* Av   = (const float*)d_in[3];
    float* out = (float*)d_out;

    const int PROJ_SMEM = (128*132 + 128*64) * 4;          // 100,352 B
    // 2 tiles + c + one padded row (prefetch overrun target) + c pad
    const int ATTN_SMEM = (2*64*Uq + 64 + Uq + 8) * 4;     //  16,800 B
    cudaFuncSetAttribute(proj_kernel,
        cudaFuncAttributeMaxDynamicSharedMemorySize, PROJ_SMEM);
    cudaFuncSetAttribute(attn_kernel,
        cudaFuncAttributeMaxDynamicSharedMemorySize, ATTN_SMEM);

    proj_kernel<<<dim3(Bq*Nq/128, Hq), 512, PROJ_SMEM>>>(inp, Wsrc, Wdst);
    attn_kernel<<<dim3(Nq/64, NJC, Bq*Hq), 128, ATTN_SMEM>>>(Av);
    combine_kernel<<<Bq*Hq*Nq*2/256, 256>>>(out);
}